// round 1
// baseline (speedup 1.0000x reference)
#include <cuda_runtime.h>
#include <cuda_fp16.h>
#include <cstdint>

#define B_  8
#define T_  200
#define U_  50
#define DE  512
#define DP  640
#define DJ  640
#define V_  1024

// Scratch for projected enc/pred activations (fp32, exact).
__device__ float g_enc[B_ * T_ * DJ];    // 4.096 MB
__device__ float g_pred[B_ * U_ * DJ];   // 1.024 MB

// ---------------------------------------------------------------------------
// Projection GEMM: C[M,J] = A[M,D] @ W[J,D]^T + bias[J]   (fp32, tiled 64x64)
// ---------------------------------------------------------------------------
__global__ void proj_kernel(const float* __restrict__ A, const float* __restrict__ W,
                            const float* __restrict__ bias, float* __restrict__ C,
                            int M, int D, int J) {
    __shared__ float As[64][17];
    __shared__ float Ws[64][17];
    int tid = threadIdx.x;
    int tx = tid & 15, ty = tid >> 4;
    int m0 = blockIdx.y * 64;
    int j0 = blockIdx.x * 64;

    float acc[4][4];
    #pragma unroll
    for (int i = 0; i < 4; i++)
        #pragma unroll
        for (int j = 0; j < 4; j++) acc[i][j] = 0.f;

    for (int kt = 0; kt < D; kt += 16) {
        #pragma unroll
        for (int i = 0; i < 4; i++) {
            int idx = tid + i * 256;
            int r = idx >> 4, k = idx & 15;
            int m = m0 + r;
            As[r][k] = (m < M) ? A[(size_t)m * D + kt + k] : 0.f;
            int j = j0 + r;
            Ws[r][k] = (j < J) ? W[(size_t)j * D + kt + k] : 0.f;
        }
        __syncthreads();
        #pragma unroll
        for (int kk = 0; kk < 16; kk++) {
            float a[4], w[4];
            #pragma unroll
            for (int i = 0; i < 4; i++) a[i] = As[ty + i * 16][kk];
            #pragma unroll
            for (int j = 0; j < 4; j++) w[j] = Ws[tx + j * 16][kk];
            #pragma unroll
            for (int i = 0; i < 4; i++)
                #pragma unroll
                for (int j = 0; j < 4; j++) acc[i][j] += a[i] * w[j];
        }
        __syncthreads();
    }
    #pragma unroll
    for (int i = 0; i < 4; i++) {
        int m = m0 + ty + i * 16;
        if (m >= M) continue;
        #pragma unroll
        for (int j = 0; j < 4; j++) {
            int jj = j0 + tx + j * 16;
            if (jj < J) C[(size_t)m * J + jj] = acc[i][j] + bias[jj];
        }
    }
}

// ---------------------------------------------------------------------------
// Fused joint GEMM:
//   out[b,t,u,n] = sum_k tanh(enc[b,t,k] + pred[b,u,k]) * W_out[n,k] + b_out[n]
// CTA tile: M=128 rows (16 t x 8 u) x N=128 vocab cols, K-chunks of 32.
// 256 threads = 8 warps (4 m-warps x 2 n-warps), mma.sync.m16n8k16 f16/f32.
// ---------------------------------------------------------------------------
__global__ __launch_bounds__(256, 2)
void joint_kernel(const float* __restrict__ Wout, const float* __restrict__ bout,
                  float* __restrict__ out) {
    // padded stride 40 halves (= 20 b32 words) -> conflict-free frag loads
    __shared__ __half As[128 * 40];
    __shared__ __half Ws[128 * 40];
    __shared__ float  enc_c[16 * 32];
    __shared__ float  pred_c[8 * 32];

    int tid  = threadIdx.x;
    int wid  = tid >> 5, lane = tid & 31;
    int g    = lane >> 2, tg = lane & 3;
    int warp_m = wid >> 1, warp_n = wid & 1;

    int nb = blockIdx.x;          // vocab tile 0..7
    int tt = blockIdx.y;          // t tile 0..12
    int z  = blockIdx.z;          // b*7 + u-tile
    int b  = z / 7, ut = z % 7;
    int t0 = tt * 16, u0 = ut * 8, n0 = nb * 128;

    const float* encp  = g_enc  + (size_t)b * T_ * DJ;
    const float* predp = g_pred + (size_t)b * U_ * DJ;

    float acc[2][8][4];
    #pragma unroll
    for (int mt = 0; mt < 2; mt++)
        #pragma unroll
        for (int nt = 0; nt < 8; nt++)
            #pragma unroll
            for (int c = 0; c < 4; c++) acc[mt][nt][c] = 0.f;

    for (int kc = 0; kc < DJ; kc += 32) {
        // W_out chunk: 128 n x 32 k (fp32 -> fp16)
        #pragma unroll
        for (int i = 0; i < 16; i++) {
            int idx = tid + i * 256;
            int n = idx >> 5, k = idx & 31;
            Ws[n * 40 + k] = __float2half(Wout[(size_t)(n0 + n) * DJ + kc + k]);
        }
        // enc chunk: 16 t x 32 k
        #pragma unroll
        for (int i = 0; i < 2; i++) {
            int idx = tid + i * 256;
            int tl = idx >> 5, k = idx & 31;
            int t = t0 + tl;
            enc_c[idx] = (t < T_) ? encp[(size_t)t * DJ + kc + k] : 0.f;
        }
        // pred chunk: 8 u x 32 k
        {
            int ul = tid >> 5, k = tid & 31;
            int u = u0 + ul;
            pred_c[tid] = (u < U_) ? predp[(size_t)u * DJ + kc + k] : 0.f;
        }
        __syncthreads();

        // A = tanh(enc + pred): 128 rows x 32 k  (row = tl*8 + ul)
        #pragma unroll
        for (int i = 0; i < 16; i++) {
            int idx = tid + i * 256;
            int row = idx >> 5, k = idx & 31;
            float v = tanhf(enc_c[(row >> 3) * 32 + k] + pred_c[(row & 7) * 32 + k]);
            As[row * 40 + k] = __float2half(v);
        }
        __syncthreads();

        const uint32_t* As32 = (const uint32_t*)As;  // word stride 20
        const uint32_t* Ws32 = (const uint32_t*)Ws;
        #pragma unroll
        for (int ks = 0; ks < 2; ks++) {
            uint32_t bfr[8][2];
            #pragma unroll
            for (int nt = 0; nt < 8; nt++) {
                int nrow = warp_n * 64 + nt * 8 + g;
                bfr[nt][0] = Ws32[nrow * 20 + ks * 8 + tg];
                bfr[nt][1] = Ws32[nrow * 20 + ks * 8 + tg + 4];
            }
            #pragma unroll
            for (int mt = 0; mt < 2; mt++) {
                int mrow = warp_m * 32 + mt * 16;
                uint32_t a0 = As32[(mrow + g)     * 20 + ks * 8 + tg];
                uint32_t a1 = As32[(mrow + g + 8) * 20 + ks * 8 + tg];
                uint32_t a2 = As32[(mrow + g)     * 20 + ks * 8 + tg + 4];
                uint32_t a3 = As32[(mrow + g + 8) * 20 + ks * 8 + tg + 4];
                #pragma unroll
                for (int nt = 0; nt < 8; nt++) {
                    asm volatile(
                        "mma.sync.aligned.m16n8k16.row.col.f32.f16.f16.f32 "
                        "{%0,%1,%2,%3}, {%4,%5,%6,%7}, {%8,%9}, {%0,%1,%2,%3};\n"
                        : "+f"(acc[mt][nt][0]), "+f"(acc[mt][nt][1]),
                          "+f"(acc[mt][nt][2]), "+f"(acc[mt][nt][3])
                        : "r"(a0), "r"(a1), "r"(a2), "r"(a3),
                          "r"(bfr[nt][0]), "r"(bfr[nt][1]));
                }
            }
        }
        __syncthreads();
    }

    // Epilogue: c0,c1 -> row g; c2,c3 -> row g+8; cols n = base + tg*2, +1
    #pragma unroll
    for (int nt = 0; nt < 8; nt++) {
        int n = n0 + warp_n * 64 + nt * 8 + tg * 2;
        float bo0 = bout[n], bo1 = bout[n + 1];
        #pragma unroll
        for (int mt = 0; mt < 2; mt++) {
            int mbase = warp_m * 32 + mt * 16;
            #pragma unroll
            for (int h = 0; h < 2; h++) {
                int row = mbase + g + h * 8;
                int tl = row >> 3, ul = row & 7;
                int t = t0 + tl, u = u0 + ul;
                if (t < T_ && u < U_) {
                    size_t base = ((((size_t)b * T_ + t) * U_ + u) * V_) + n;
                    out[base]     = acc[mt][nt][h * 2]     + bo0;
                    out[base + 1] = acc[mt][nt][h * 2 + 1] + bo1;
                }
            }
        }
    }
}

// ---------------------------------------------------------------------------
extern "C" void kernel_launch(void* const* d_in, const int* in_sizes, int n_in,
                              void* d_out, int out_size) {
    const float* encoder_out   = (const float*)d_in[0];
    const float* predictor_out = (const float*)d_in[1];
    const float* W_enc  = (const float*)d_in[2];
    const float* b_enc  = (const float*)d_in[3];
    const float* W_pred = (const float*)d_in[4];
    const float* b_pred = (const float*)d_in[5];
    const float* W_out  = (const float*)d_in[6];
    const float* b_out  = (const float*)d_in[7];
    float* out = (float*)d_out;

    float* enc_buf;
    float* pred_buf;
    cudaGetSymbolAddress((void**)&enc_buf,  g_enc);
    cudaGetSymbolAddress((void**)&pred_buf, g_pred);

    // enc projection: (1600,512)@(640,512)^T
    {
        dim3 grid(DJ / 64, (B_ * T_ + 63) / 64);
        proj_kernel<<<grid, 256>>>(encoder_out, W_enc, b_enc, enc_buf,
                                   B_ * T_, DE, DJ);
    }
    // pred projection: (400,640)@(640,640)^T
    {
        dim3 grid(DJ / 64, (B_ * U_ + 63) / 64);
        proj_kernel<<<grid, 256>>>(predictor_out, W_pred, b_pred, pred_buf,
                                   B_ * U_, DP, DJ);
    }
    // fused joint GEMM
    {
        dim3 grid(V_ / 128, (T_ + 15) / 16, B_ * ((U_ + 7) / 8));  // 8 x 13 x 56
        joint_kernel<<<grid, 256>>>(W_out, b_out, out);
    }
}

// round 3
// speedup vs baseline: 1.9376x; 1.9376x over previous
#include <cuda_runtime.h>
#include <cuda_fp16.h>
#include <cstdint>

#define B_  8
#define T_  200
#define U_  50
#define DE  512
#define DP  640
#define DJ  640
#define V_  1024

#define SA  648   // As stride in halves (324 words, 324%32=4 -> conflict-free)
#define SAW 324
#define SW  72    // Ws stride in halves (36 words, %32=4)
#define SWW 36

// Scratch
__device__ float  g_enc [B_ * T_ * DJ];   // 4.1 MB
__device__ float  g_pred[B_ * U_ * DJ];   // 1.0 MB
__device__ __half g_wh  [V_ * DJ];        // 1.3 MB

// ---------------------------------------------------------------------------
// W_out fp32 -> fp16
// ---------------------------------------------------------------------------
__global__ void convert_w_kernel(const float* __restrict__ W, __half* __restrict__ Wh) {
    int i = blockIdx.x * blockDim.x + threadIdx.x;
    if (i < V_ * DJ / 2) {
        float2 v = ((const float2*)W)[i];
        ((half2*)Wh)[i] = __floats2half2_rn(v.x, v.y);
    }
}

// ---------------------------------------------------------------------------
// Projection GEMM: C[M,J] = A[M,D] @ W[J,D]^T + bias, fp32, 32x64 tiles
// ---------------------------------------------------------------------------
__global__ __launch_bounds__(256)
void proj_kernel(const float* __restrict__ A, const float* __restrict__ W,
                 const float* __restrict__ bias, float* __restrict__ C,
                 int M, int D, int J) {
    __shared__ float As[32][17];
    __shared__ float Ws[64][17];
    int tid = threadIdx.x;
    int tx = tid & 15, ty = tid >> 4;
    int m0 = blockIdx.y * 32;
    int j0 = blockIdx.x * 64;

    float acc[2][4];
    #pragma unroll
    for (int i = 0; i < 2; i++)
        #pragma unroll
        for (int j = 0; j < 4; j++) acc[i][j] = 0.f;

    for (int kt = 0; kt < D; kt += 16) {
        #pragma unroll
        for (int i = 0; i < 2; i++) {
            int idx = tid + i * 256;
            int r = idx >> 4, k = idx & 15;
            int m = m0 + r;
            As[r][k] = (m < M) ? A[(size_t)m * D + kt + k] : 0.f;
        }
        #pragma unroll
        for (int i = 0; i < 4; i++) {
            int idx = tid + i * 256;
            int r = idx >> 4, k = idx & 15;
            Ws[r][k] = W[(size_t)(j0 + r) * D + kt + k];
        }
        __syncthreads();
        #pragma unroll
        for (int kk = 0; kk < 16; kk++) {
            float a0 = As[ty][kk], a1 = As[ty + 16][kk];
            float w[4];
            #pragma unroll
            for (int j = 0; j < 4; j++) w[j] = Ws[tx + j * 16][kk];
            #pragma unroll
            for (int j = 0; j < 4; j++) {
                acc[0][j] += a0 * w[j];
                acc[1][j] += a1 * w[j];
            }
        }
        __syncthreads();
    }
    #pragma unroll
    for (int i = 0; i < 2; i++) {
        int m = m0 + ty + i * 16;
        if (m >= M) continue;
        #pragma unroll
        for (int j = 0; j < 4; j++) {
            int jj = j0 + tx + j * 16;
            C[(size_t)m * J + jj] = acc[i][j] + bias[jj];
        }
    }
}

// ---------------------------------------------------------------------------
// Fused joint GEMM, one CTA = 128-row M-tile x full V=1024, A persistent.
// ---------------------------------------------------------------------------
__device__ __forceinline__ uint32_t smem_u32(const void* p) {
    return (uint32_t)__cvta_generic_to_shared(p);
}
__device__ __forceinline__ void ldsm_x4(uint32_t& r0, uint32_t& r1, uint32_t& r2,
                                        uint32_t& r3, uint32_t a) {
    asm volatile("ldmatrix.sync.aligned.m8n8.x4.shared.b16 {%0,%1,%2,%3}, [%4];\n"
                 : "=r"(r0), "=r"(r1), "=r"(r2), "=r"(r3) : "r"(a));
}
__device__ __forceinline__ void cp16(uint32_t dst, const void* src) {
    asm volatile("cp.async.cg.shared.global [%0], [%1], 16;\n" :: "r"(dst), "l"(src));
}

extern __shared__ char dynsmem[];

#define JOINT_SMEM (128 * SA * 2 + 2 * 128 * SW * 2 + 16 * 64 * 4 + 8 * 64 * 4)

__global__ __launch_bounds__(512, 1)
void joint_kernel(const float* __restrict__ bout, float* __restrict__ out) {
    half*  As    = (half*)dynsmem;                 // 128 x SA
    half*  Ws    = As + 128 * SA;                  // 2 x 128 x SW
    float* encs  = (float*)(Ws + 2 * 128 * SW);    // 16 x 64
    float* preds = encs + 16 * 64;                 // 8 x 64

    int tid = threadIdx.x;
    int wid = tid >> 5, lane = tid & 31;
    int g = lane >> 2, tg = lane & 3;
    int warp_m = wid >> 2, warp_n = wid & 3;

    int bx = blockIdx.x;                 // 0..727
    int b = bx / 91;
    int r = bx % 91;
    int tt = r % 13, ut = r / 13;
    int t0 = tt * 16, u0 = ut * 8;

    const float* encp  = g_enc  + (size_t)b * T_ * DJ;
    const float* predp = g_pred + (size_t)b * U_ * DJ;

    uint32_t as_u = smem_u32(As);
    uint32_t ws_u = smem_u32(Ws);

    // W chunk prefetch: step s -> vocab tile s/10, k-chunk (s%10)*64
    auto loadw = [&](int s) {
        int buf = s & 1;
        int n0 = (s / 10) * 128;
        int kc = (s % 10) * 64;
        const half* src_base = g_wh + (size_t)n0 * DJ + kc;
        #pragma unroll
        for (int i = 0; i < 2; i++) {
            int idx = tid + i * 512;
            int row = idx >> 3, seg = idx & 7;
            uint32_t dst = ws_u + (uint32_t)(buf * 128 * SW + row * SW + seg * 8) * 2;
            cp16(dst, src_base + (size_t)row * DJ + seg * 8);
        }
    };
    loadw(0); asm volatile("cp.async.commit_group;\n" ::: "memory");
    loadw(1); asm volatile("cp.async.commit_group;\n" ::: "memory");

    // ---- Phase 1: A = tanh(enc + pred), fp16, computed ONCE ----
    for (int kc = 0; kc < DJ; kc += 64) {
        {   // enc 16x64 floats: 512 float2, one per thread
            int tl = tid >> 5, kp = tid & 31;
            int t = t0 + tl;
            float2 v = make_float2(0.f, 0.f);
            if (t < T_) v = *(const float2*)(encp + (size_t)t * DJ + kc + kp * 2);
            *(float2*)(encs + tl * 64 + kp * 2) = v;
        }
        if (tid < 256) {  // pred 8x64: 256 float2
            int ul = tid >> 5, kp = tid & 31;
            int u = u0 + ul;
            float2 v = make_float2(0.f, 0.f);
            if (u < U_) v = *(const float2*)(predp + (size_t)u * DJ + kc + kp * 2);
            *(float2*)(preds + ul * 64 + kp * 2) = v;
        }
        __syncthreads();
        #pragma unroll
        for (int i = 0; i < 8; i++) {
            int idx = tid + i * 512;
            int row = idx >> 5, kp = idx & 31;
            float2 e = *(const float2*)(encs + ((row >> 3) << 6) + kp * 2);
            float2 p = *(const float2*)(preds + ((row & 7) << 6) + kp * 2);
            half2 h = __floats2half2_rn(tanhf(e.x + p.x), tanhf(e.y + p.y));
            *(half2*)(As + row * SA + kc + kp * 2) = h;
        }
        __syncthreads();
    }

    // ---- Phase 2: loop 8 vocab tiles x 10 K-chunks of 64 ----
    float acc[2][4][4];
    #pragma unroll
    for (int mt = 0; mt < 2; mt++)
        #pragma unroll
        for (int nt = 0; nt < 4; nt++)
            #pragma unroll
            for (int c = 0; c < 4; c++) acc[mt][nt][c] = 0.f;

    int nb = 0;
    for (int step = 0; step < 80; ++step) {
        asm volatile("cp.async.wait_group 1;\n" ::: "memory");
        __syncthreads();

        int buf = step & 1;
        int kw0 = (step % 10) * 32;                       // word offset in As row
        uint32_t wbase = ws_u + (uint32_t)(buf * 128 * SW) * 2;

        #pragma unroll
        for (int ks = 0; ks < 4; ks++) {
            uint32_t a[2][4];
            #pragma unroll
            for (int mt = 0; mt < 2; mt++) {
                int j = lane >> 3;
                int row = warp_m * 32 + mt * 16 + (lane & 7) + (j & 1) * 8;
                int col = kw0 + ks * 8 + (j >> 1) * 4;
                ldsm_x4(a[mt][0], a[mt][1], a[mt][2], a[mt][3],
                        as_u + (uint32_t)(row * SAW + col) * 4);
            }
            uint32_t bb[2][4];
            #pragma unroll
            for (int np = 0; np < 2; np++) {
                int j = lane >> 3;
                int row = warp_n * 32 + np * 16 + (j >> 1) * 8 + (lane & 7);
                int col = ks * 8 + (j & 1) * 4;
                ldsm_x4(bb[np][0], bb[np][1], bb[np][2], bb[np][3],
                        wbase + (uint32_t)(row * SWW + col) * 4);
            }
            #pragma unroll
            for (int mt = 0; mt < 2; mt++) {
                #pragma unroll
                for (int nt = 0; nt < 4; nt++) {
                    uint32_t bf0 = bb[nt >> 1][(nt & 1) * 2];
                    uint32_t bf1 = bb[nt >> 1][(nt & 1) * 2 + 1];
                    asm volatile(
                        "mma.sync.aligned.m16n8k16.row.col.f32.f16.f16.f32 "
                        "{%0,%1,%2,%3}, {%4,%5,%6,%7}, {%8,%9}, {%0,%1,%2,%3};\n"
                        : "+f"(acc[mt][nt][0]), "+f"(acc[mt][nt][1]),
                          "+f"(acc[mt][nt][2]), "+f"(acc[mt][nt][3])
                        : "r"(a[mt][0]), "r"(a[mt][1]), "r"(a[mt][2]), "r"(a[mt][3]),
                          "r"(bf0), "r"(bf1));
                }
            }
        }
        __syncthreads();

        if (step + 2 < 80) loadw(step + 2);
        asm volatile("cp.async.commit_group;\n" ::: "memory");

        if ((step % 10) == 9) {
            // epilogue for vocab tile nb
            int n0 = nb * 128;
            #pragma unroll
            for (int nt = 0; nt < 4; nt++) {
                int n = n0 + warp_n * 32 + nt * 8 + tg * 2;
                float bo0 = __ldg(bout + n);
                float bo1 = __ldg(bout + n + 1);
                #pragma unroll
                for (int mt = 0; mt < 2; mt++) {
                    #pragma unroll
                    for (int h = 0; h < 2; h++) {
                        int row = warp_m * 32 + mt * 16 + g + h * 8;
                        int t = t0 + (row >> 3), u = u0 + (row & 7);
                        if (t < T_ && u < U_) {
                            size_t base = ((((size_t)b * T_ + t) * U_ + u) * V_) + n;
                            float2 v = make_float2(acc[mt][nt][h * 2] + bo0,
                                                   acc[mt][nt][h * 2 + 1] + bo1);
                            *(float2*)(out + base) = v;
                        }
                    }
                }
            }
            nb++;
            #pragma unroll
            for (int mt = 0; mt < 2; mt++)
                #pragma unroll
                for (int nt = 0; nt < 4; nt++)
                    #pragma unroll
                    for (int c = 0; c < 4; c++) acc[mt][nt][c] = 0.f;
        }
    }
    // drain any outstanding async copies before CTA exit
    asm volatile("cp.async.wait_group 0;\n" ::: "memory");
}

// ---------------------------------------------------------------------------
extern "C" void kernel_launch(void* const* d_in, const int* in_sizes, int n_in,
                              void* d_out, int out_size) {
    const float* encoder_out   = (const float*)d_in[0];
    const float* predictor_out = (const float*)d_in[1];
    const float* W_enc  = (const float*)d_in[2];
    const float* b_enc  = (const float*)d_in[3];
    const float* W_pred = (const float*)d_in[4];
    const float* b_pred = (const float*)d_in[5];
    const float* W_out  = (const float*)d_in[6];
    const float* b_out  = (const float*)d_in[7];
    float* out = (float*)d_out;

    float* enc_buf;
    float* pred_buf;
    __half* wh_buf;
    cudaGetSymbolAddress((void**)&enc_buf,  g_enc);
    cudaGetSymbolAddress((void**)&pred_buf, g_pred);
    cudaGetSymbolAddress((void**)&wh_buf,   g_wh);

    cudaFuncSetAttribute(joint_kernel,
                         cudaFuncAttributeMaxDynamicSharedMemorySize, JOINT_SMEM);

    // W_out -> fp16
    convert_w_kernel<<<(V_ * DJ / 2 + 255) / 256, 256>>>(W_out, wh_buf);

    // projections (fp32 exact)
    {
        dim3 grid(DJ / 64, (B_ * T_ + 31) / 32);   // 10 x 50
        proj_kernel<<<grid, 256>>>(encoder_out, W_enc, b_enc, enc_buf,
                                   B_ * T_, DE, DJ);
    }
    {
        dim3 grid(DJ / 64, (B_ * U_ + 31) / 32);   // 10 x 13
        proj_kernel<<<grid, 256>>>(predictor_out, W_pred, b_pred, pred_buf,
                                   B_ * U_, DP, DJ);
    }
    // fused joint GEMM: 728 M-tiles (13 t-tiles x 7 u-tiles x 8 b)
    joint_kernel<<<728, 512, JOINT_SMEM>>>(b_out, out);
}

// round 6
// speedup vs baseline: 2.0501x; 1.0581x over previous
#include <cuda_runtime.h>
#include <cuda_fp16.h>
#include <cstdint>

#define B_  8
#define T_  200
#define U_  50
#define DE  512
#define DP  640
#define DJ  640
#define V_  1024

// Joint tiling
#define MT    64          // M rows per CTA (8 t x 8 u)
#define NTILE 128         // vocab cols per tile
#define NT    (V_ / NTILE)      // 8 tiles
#define KC    32          // K halves per step
#define STEPS_PER_TILE (DJ / KC)  // 20
#define NSTEPS (NT * STEPS_PER_TILE)  // 160

#define SA   648          // As stride (halves); 324 words, %32=4 -> ldsm conflict-free
#define SAW  324
#define SW   40           // Ws stride (halves); 20 words, %32=20 -> conflict-free
#define SWW  20

#define AS_BYTES   (MT * SA * 2)              // 82944
#define WSTAGE     (NTILE * SW * 2)           // 10240
#define WS_OFF     AS_BYTES
#define ENC_OFF    (WS_OFF + 2 * WSTAGE)      // 103424
#define PRED_OFF   (ENC_OFF + 8 * 64 * 4)     // 105472
#define JOINT_SMEM (PRED_OFF + 8 * 64 * 4)    // 107520

// Scratch
__device__ float  g_enc [B_ * T_ * DJ];
__device__ float  g_pred[B_ * U_ * DJ];
__device__ __half g_wh  [V_ * DJ];

// ---------------------------------------------------------------------------
__device__ __forceinline__ uint32_t smem_u32(const void* p) {
    return (uint32_t)__cvta_generic_to_shared(p);
}
__device__ __forceinline__ void ldsm_x4(uint32_t& r0, uint32_t& r1, uint32_t& r2,
                                        uint32_t& r3, uint32_t a) {
    asm volatile("ldmatrix.sync.aligned.m8n8.x4.shared.b16 {%0,%1,%2,%3}, [%4];\n"
                 : "=r"(r0), "=r"(r1), "=r"(r2), "=r"(r3) : "r"(a));
}
__device__ __forceinline__ void cp16(uint32_t dst, const void* src) {
    asm volatile("cp.async.cg.shared.global [%0], [%1], 16;\n" :: "r"(dst), "l"(src));
}
__device__ __forceinline__ float tanh_fast(float x) {
    float y;
    asm("tanh.approx.f32 %0, %1;" : "=f"(y) : "f"(x));
    return y;
}

// ---------------------------------------------------------------------------
// W_out fp32 -> fp16
// ---------------------------------------------------------------------------
__global__ void convert_w_kernel(const float* __restrict__ W, __half* __restrict__ Wh) {
    int i = blockIdx.x * blockDim.x + threadIdx.x;
    if (i < V_ * DJ / 2) {
        float2 v = ((const float2*)W)[i];
        ((half2*)Wh)[i] = __floats2half2_rn(v.x, v.y);
    }
}

// ---------------------------------------------------------------------------
// Merged projection GEMMs: z=0 -> enc, z=1 -> pred. fp32, 32x64 tiles.
// ---------------------------------------------------------------------------
__global__ __launch_bounds__(256)
void proj_kernel(const float* __restrict__ Aenc, const float* __restrict__ Wenc,
                 const float* __restrict__ benc, float* __restrict__ Cenc,
                 const float* __restrict__ Apred, const float* __restrict__ Wpred,
                 const float* __restrict__ bpred, float* __restrict__ Cpred) {
    int z = blockIdx.z;
    const float* A    = z ? Apred : Aenc;
    const float* W    = z ? Wpred : Wenc;
    const float* bias = z ? bpred : benc;
    float*       C    = z ? Cpred : Cenc;
    int M = z ? (B_ * U_) : (B_ * T_);
    int D = z ? DP : DE;

    int m0 = blockIdx.y * 32;
    if (m0 >= M) return;
    int j0 = blockIdx.x * 64;

    __shared__ float As[32][17];
    __shared__ float Ws[64][17];
    int tid = threadIdx.x;
    int tx = tid & 15, ty = tid >> 4;

    float acc[2][4];
    #pragma unroll
    for (int i = 0; i < 2; i++)
        #pragma unroll
        for (int j = 0; j < 4; j++) acc[i][j] = 0.f;

    for (int kt = 0; kt < D; kt += 16) {
        #pragma unroll
        for (int i = 0; i < 2; i++) {
            int idx = tid + i * 256;
            int r = idx >> 4, k = idx & 15;
            int m = m0 + r;
            As[r][k] = (m < M) ? A[(size_t)m * D + kt + k] : 0.f;
        }
        #pragma unroll
        for (int i = 0; i < 4; i++) {
            int idx = tid + i * 256;
            int r = idx >> 4, k = idx & 15;
            Ws[r][k] = W[(size_t)(j0 + r) * D + kt + k];
        }
        __syncthreads();
        #pragma unroll
        for (int kk = 0; kk < 16; kk++) {
            float a0 = As[ty][kk], a1 = As[ty + 16][kk];
            float w[4];
            #pragma unroll
            for (int j = 0; j < 4; j++) w[j] = Ws[tx + j * 16][kk];
            #pragma unroll
            for (int j = 0; j < 4; j++) {
                acc[0][j] += a0 * w[j];
                acc[1][j] += a1 * w[j];
            }
        }
        __syncthreads();
    }
    #pragma unroll
    for (int i = 0; i < 2; i++) {
        int m = m0 + ty + i * 16;
        if (m >= M) continue;
        #pragma unroll
        for (int j = 0; j < 4; j++) {
            int jj = j0 + tx + j * 16;
            C[(size_t)m * DJ + jj] = acc[i][j] + bias[jj];
        }
    }
}

// ---------------------------------------------------------------------------
// Joint kernel: CTA = 64 M-rows (8t x 8u) x V=1024. 256 threads, 2 CTAs/SM.
// A = tanh(enc+pred) fp16 persistent in SMEM; W fp16 double-buffered (K=32).
// 8 warps = 2 m-warps x 4 n-warps; warp tile 32x32; mma.sync m16n8k16.
// ---------------------------------------------------------------------------
extern __shared__ __align__(128) char dynsmem[];

__global__ __launch_bounds__(256, 2)
void joint_kernel(const float* __restrict__ bout, float* __restrict__ out) {
    half*  As    = (half*)dynsmem;
    float* encs  = (float*)(dynsmem + ENC_OFF);    // 8 x 64
    float* preds = (float*)(dynsmem + PRED_OFF);   // 8 x 64

    int tid = threadIdx.x;
    int wid = tid >> 5, lane = tid & 31;
    int g = lane >> 2, tg = lane & 3;
    int warp_m = wid >> 2, warp_n = wid & 3;   // 2 x 4

    int bx = blockIdx.x;               // 1400 CTAs: 25 t-tiles x 7 u-tiles x 8 b
    int b = bx / 175, r = bx % 175;
    int tt = r % 25, ut = r / 25;
    int t0 = tt * 8, u0 = ut * 8;

    uint32_t as_u = smem_u32(As);
    uint32_t ws_u = as_u + WS_OFF;

    // Prefetch W stage for step s: vocab tile s/20, kc = (s%20)*32 halves.
    auto loadw = [&](int s) {
        int buf = s & 1;
        const half* src = g_wh + (size_t)(s / STEPS_PER_TILE) * NTILE * DJ
                               + (s % STEPS_PER_TILE) * KC;
        uint32_t dstb = ws_u + (uint32_t)buf * WSTAGE;
        #pragma unroll
        for (int i = 0; i < 2; i++) {
            int c = tid + i * 256;           // 512 chunks: 128 rows x 4 x 16B
            int row = c >> 2, seg = c & 3;
            cp16(dstb + (uint32_t)(row * SW + seg * 8) * 2,
                 src + (size_t)row * DJ + seg * 8);
        }
    };
    loadw(0); asm volatile("cp.async.commit_group;\n" ::: "memory");
    loadw(1); asm volatile("cp.async.commit_group;\n" ::: "memory");

    // ---- Phase 1: A = tanh(enc + pred), fp16, once ----
    const float* encp  = g_enc  + ((size_t)b * T_ + t0) * DJ;
    const float* predp = g_pred + ((size_t)b * U_ + u0) * DJ;
    for (int kc = 0; kc < DJ; kc += 64) {
        {   // enc 8x64: 256 float2, one per thread
            int rw = tid >> 5, kp = tid & 31;
            *(float2*)(encs + rw * 64 + kp * 2) =
                *(const float2*)(encp + (size_t)rw * DJ + kc + kp * 2);
            int u = u0 + rw;
            float2 pv = make_float2(0.f, 0.f);
            if (u < U_) pv = *(const float2*)(predp + (size_t)rw * DJ + kc + kp * 2);
            *(float2*)(preds + rw * 64 + kp * 2) = pv;
        }
        __syncthreads();
        #pragma unroll
        for (int i = 0; i < 8; i++) {
            int idx = tid + i * 256;
            int row = idx >> 5, kp = idx & 31;     // row = t-local*8 + u-local
            float2 e = *(const float2*)(encs + ((row >> 3) << 6) + kp * 2);
            float2 p = *(const float2*)(preds + ((row & 7) << 6) + kp * 2);
            half2 h = __floats2half2_rn(tanh_fast(e.x + p.x), tanh_fast(e.y + p.y));
            *(half2*)(As + row * SA + kc + kp * 2) = h;
        }
        __syncthreads();
    }

    // ---- Phase 2: 8 vocab tiles x 20 K-steps, double-buffered W ----
    float acc[2][4][4];
    #pragma unroll
    for (int mt = 0; mt < 2; mt++)
        #pragma unroll
        for (int nt = 0; nt < 4; nt++)
            #pragma unroll
            for (int c = 0; c < 4; c++) acc[mt][nt][c] = 0.f;

    int j = lane >> 3;
    int a_row_base = warp_m * 32 + (lane & 7) + (j & 1) * 8;
    int a_col_base = (j >> 1) * 4;
    int b_row_base = warp_n * 32 + (j >> 1) * 8 + (lane & 7);
    int b_col_base = (j & 1) * 4;

    for (int s = 0; s < NSTEPS; ++s) {
        asm volatile("cp.async.wait_group 1;\n" ::: "memory");
        __syncthreads();

        int kw0 = (s % STEPS_PER_TILE) * (KC / 2);     // word offset in As row
        uint32_t wbase = ws_u + (uint32_t)(s & 1) * WSTAGE;

        #pragma unroll
        for (int ks = 0; ks < 2; ks++) {
            uint32_t a[2][4];
            #pragma unroll
            for (int mt = 0; mt < 2; mt++)
                ldsm_x4(a[mt][0], a[mt][1], a[mt][2], a[mt][3],
                        as_u + (uint32_t)((a_row_base + mt * 16) * SAW
                                          + kw0 + ks * 8 + a_col_base) * 4);
            uint32_t bb[2][4];
            #pragma unroll
            for (int np = 0; np < 2; np++)
                ldsm_x4(bb[np][0], bb[np][1], bb[np][2], bb[np][3],
                        wbase + (uint32_t)((b_row_base + np * 16) * SWW
                                           + ks * 8 + b_col_base) * 4);
            #pragma unroll
            for (int mt = 0; mt < 2; mt++) {
                #pragma unroll
                for (int nt = 0; nt < 4; nt++) {
                    uint32_t bf0 = bb[nt >> 1][(nt & 1) * 2];
                    uint32_t bf1 = bb[nt >> 1][(nt & 1) * 2 + 1];
                    asm volatile(
                        "mma.sync.aligned.m16n8k16.row.col.f32.f16.f16.f32 "
                        "{%0,%1,%2,%3}, {%4,%5,%6,%7}, {%8,%9}, {%0,%1,%2,%3};\n"
                        : "+f"(acc[mt][nt][0]), "+f"(acc[mt][nt][1]),
                          "+f"(acc[mt][nt][2]), "+f"(acc[mt][nt][3])
                        : "r"(a[mt][0]), "r"(a[mt][1]), "r"(a[mt][2]), "r"(a[mt][3]),
                          "r"(bf0), "r"(bf1));
                }
            }
        }
        __syncthreads();

        if (s + 2 < NSTEPS) loadw(s + 2);
        asm volatile("cp.async.commit_group;\n" ::: "memory");

        if ((s % STEPS_PER_TILE) == STEPS_PER_TILE - 1) {
            int n0 = (s / STEPS_PER_TILE) * NTILE;
            #pragma unroll
            for (int nt = 0; nt < 4; nt++) {
                int n = n0 + warp_n * 32 + nt * 8 + tg * 2;
                float bo0 = __ldg(bout + n);
                float bo1 = __ldg(bout + n + 1);
                #pragma unroll
                for (int mt = 0; mt < 2; mt++) {
                    #pragma unroll
                    for (int h = 0; h < 2; h++) {
                        int row = warp_m * 32 + mt * 16 + g + h * 8;
                        int t = t0 + (row >> 3), u = u0 + (row & 7);
                        if (u < U_) {
                            size_t base = ((((size_t)b * T_ + t) * U_ + u) * V_) + n;
                            float2 v = make_float2(acc[mt][nt][h * 2] + bo0,
                                                   acc[mt][nt][h * 2 + 1] + bo1);
                            *(float2*)(out + base) = v;
                        }
                    }
                }
            }
            #pragma unroll
            for (int mt = 0; mt < 2; mt++)
                #pragma unroll
                for (int nt = 0; nt < 4; nt++)
                    #pragma unroll
                    for (int c = 0; c < 4; c++) acc[mt][nt][c] = 0.f;
        }
    }
    asm volatile("cp.async.wait_group 0;\n" ::: "memory");
}

// ---------------------------------------------------------------------------
extern "C" void kernel_launch(void* const* d_in, const int* in_sizes, int n_in,
                              void* d_out, int out_size) {
    const float* encoder_out   = (const float*)d_in[0];
    const float* predictor_out = (const float*)d_in[1];
    const float* W_enc  = (const float*)d_in[2];
    const float* b_enc  = (const float*)d_in[3];
    const float* W_pred = (const float*)d_in[4];
    const float* b_pred = (const float*)d_in[5];
    const float* W_out  = (const float*)d_in[6];
    const float* b_out  = (const float*)d_in[7];
    float* out = (float*)d_out;

    float* enc_buf;
    float* pred_buf;
    __half* wh_buf;
    cudaGetSymbolAddress((void**)&enc_buf,  g_enc);
    cudaGetSymbolAddress((void**)&pred_buf, g_pred);
    cudaGetSymbolAddress((void**)&wh_buf,   g_wh);

    cudaFuncSetAttribute(joint_kernel,
                         cudaFuncAttributeMaxDynamicSharedMemorySize, JOINT_SMEM);

    convert_w_kernel<<<(V_ * DJ / 2 + 255) / 256, 256>>>(W_out, wh_buf);

    {   // merged projections: z=0 enc (50 y-tiles), z=1 pred (13 y-tiles)
        dim3 grid(DJ / 64, (B_ * T_ + 31) / 32, 2);
        proj_kernel<<<grid, 256>>>(encoder_out, W_enc, b_enc, enc_buf,
                                   predictor_out, W_pred, b_pred, pred_buf);
    }

    // joint: 25 t-tiles x 7 u-tiles x 8 b = 1400 CTAs, 2 per SM
    joint_kernel<<<1400, 256, JOINT_SMEM>>>(b_out, out);
}

// round 7
// speedup vs baseline: 2.0583x; 1.0040x over previous
#include <cuda_runtime.h>
#include <cuda_fp16.h>
#include <cstdint>

#define B_  8
#define T_  200
#define U_  50
#define DE  512
#define DP  640
#define DJ  640
#define V_  1024

// Joint tiling: CTA = 128 M-rows x 256 vocab cols per tile, 4 tiles.
#define MT    128
#define NTILE 256
#define NT    (V_ / NTILE)            // 4
#define KC    32                      // K halves per step
#define STEPS_PER_TILE (DJ / KC)      // 20
#define NSTEPS (NT * STEPS_PER_TILE)  // 80

#define SA   648   // As stride halves; 324 words, %32=4 -> ldsm conflict-free
#define SAW  324
#define SW   40    // Ws stride halves; 20 words, %32=20 -> conflict-free
#define SWW  20

#define AS_BYTES   (MT * SA * 2)               // 165888
#define WSTAGE     (NTILE * SW * 2)            // 20480
#define WS_OFF     AS_BYTES
#define ENC_OFF    (WS_OFF + 2 * WSTAGE)       // 206848
#define PRED_OFF   (ENC_OFF + 16 * 64 * 4)     // 210944
#define JOINT_SMEM (PRED_OFF + 8 * 64 * 4)     // 212992

// Scratch
__device__ float  g_enc [B_ * T_ * DJ];
__device__ float  g_pred[B_ * U_ * DJ];
__device__ __half g_wh  [V_ * DJ];

// ---------------------------------------------------------------------------
__device__ __forceinline__ uint32_t smem_u32(const void* p) {
    return (uint32_t)__cvta_generic_to_shared(p);
}
__device__ __forceinline__ void ldsm_x4(uint32_t& r0, uint32_t& r1, uint32_t& r2,
                                        uint32_t& r3, uint32_t a) {
    asm volatile("ldmatrix.sync.aligned.m8n8.x4.shared.b16 {%0,%1,%2,%3}, [%4];\n"
                 : "=r"(r0), "=r"(r1), "=r"(r2), "=r"(r3) : "r"(a));
}
__device__ __forceinline__ void cp16(uint32_t dst, const void* src) {
    asm volatile("cp.async.cg.shared.global [%0], [%1], 16;\n" :: "r"(dst), "l"(src));
}
__device__ __forceinline__ float tanh_fast(float x) {
    float y;
    asm("tanh.approx.f32 %0, %1;" : "=f"(y) : "f"(x));
    return y;
}

// ---------------------------------------------------------------------------
// W_out fp32 -> fp16
// ---------------------------------------------------------------------------
__global__ void convert_w_kernel(const float* __restrict__ W, __half* __restrict__ Wh) {
    int i = blockIdx.x * blockDim.x + threadIdx.x;
    if (i < V_ * DJ / 2) {
        float2 v = ((const float2*)W)[i];
        ((half2*)Wh)[i] = __floats2half2_rn(v.x, v.y);
    }
}

// ---------------------------------------------------------------------------
// Merged projection GEMMs: z=0 -> enc, z=1 -> pred. fp32, 32x64 tiles.
// ---------------------------------------------------------------------------
__global__ __launch_bounds__(256)
void proj_kernel(const float* __restrict__ Aenc, const float* __restrict__ Wenc,
                 const float* __restrict__ benc, float* __restrict__ Cenc,
                 const float* __restrict__ Apred, const float* __restrict__ Wpred,
                 const float* __restrict__ bpred, float* __restrict__ Cpred) {
    int z = blockIdx.z;
    const float* A    = z ? Apred : Aenc;
    const float* W    = z ? Wpred : Wenc;
    const float* bias = z ? bpred : benc;
    float*       C    = z ? Cpred : Cenc;
    int M = z ? (B_ * U_) : (B_ * T_);
    int D = z ? DP : DE;

    int m0 = blockIdx.y * 32;
    if (m0 >= M) return;
    int j0 = blockIdx.x * 64;

    __shared__ float As[32][17];
    __shared__ float Ws[64][17];
    int tid = threadIdx.x;
    int tx = tid & 15, ty = tid >> 4;

    float acc[2][4];
    #pragma unroll
    for (int i = 0; i < 2; i++)
        #pragma unroll
        for (int j = 0; j < 4; j++) acc[i][j] = 0.f;

    for (int kt = 0; kt < D; kt += 16) {
        #pragma unroll
        for (int i = 0; i < 2; i++) {
            int idx = tid + i * 256;
            int r = idx >> 4, k = idx & 15;
            int m = m0 + r;
            As[r][k] = (m < M) ? A[(size_t)m * D + kt + k] : 0.f;
        }
        #pragma unroll
        for (int i = 0; i < 4; i++) {
            int idx = tid + i * 256;
            int r = idx >> 4, k = idx & 15;
            Ws[r][k] = W[(size_t)(j0 + r) * D + kt + k];
        }
        __syncthreads();
        #pragma unroll
        for (int kk = 0; kk < 16; kk++) {
            float a0 = As[ty][kk], a1 = As[ty + 16][kk];
            float w[4];
            #pragma unroll
            for (int j = 0; j < 4; j++) w[j] = Ws[tx + j * 16][kk];
            #pragma unroll
            for (int j = 0; j < 4; j++) {
                acc[0][j] += a0 * w[j];
                acc[1][j] += a1 * w[j];
            }
        }
        __syncthreads();
    }
    #pragma unroll
    for (int i = 0; i < 2; i++) {
        int m = m0 + ty + i * 16;
        if (m >= M) continue;
        #pragma unroll
        for (int j = 0; j < 4; j++) {
            int jj = j0 + tx + j * 16;
            C[(size_t)m * DJ + jj] = acc[i][j] + bias[jj];
        }
    }
}

// ---------------------------------------------------------------------------
// Joint kernel: CTA = 128 M-rows (16t x 8u) x V=1024 in 4 tiles of N=256.
// 256 threads = 8 warps as 2m x 4n; warp tile 64x64 (big tiles -> low LDS/MAC).
// A = tanh(enc+pred) fp16 persistent in SMEM; W fp16 double-buffered (K=32).
// ---------------------------------------------------------------------------
extern __shared__ __align__(128) char dynsmem[];

__global__ __launch_bounds__(256, 1)
void joint_kernel(const float* __restrict__ bout, float* __restrict__ out) {
    half*  As    = (half*)dynsmem;
    float* encs  = (float*)(dynsmem + ENC_OFF);    // 16 x 64
    float* preds = (float*)(dynsmem + PRED_OFF);   // 8 x 64

    int tid = threadIdx.x;
    int wid = tid >> 5, lane = tid & 31;
    int g = lane >> 2, tg = lane & 3;
    int warp_m = wid >> 2, warp_n = wid & 3;   // 2 x 4

    int bx = blockIdx.x;               // 728 CTAs: 13 t-tiles x 7 u-tiles x 8 b
    int b = bx / 91, r = bx % 91;
    int tt = r % 13, ut = r / 13;
    int t0 = tt * 16, u0 = ut * 8;

    uint32_t as_u = smem_u32(As);
    uint32_t ws_u = as_u + WS_OFF;

    // Prefetch W stage for step s: vocab tile s/20 (N=256), kc = (s%20)*32 halves.
    auto loadw = [&](int s) {
        int buf = s & 1;
        const half* src = g_wh + (size_t)(s / STEPS_PER_TILE) * NTILE * DJ
                               + (s % STEPS_PER_TILE) * KC;
        uint32_t dstb = ws_u + (uint32_t)buf * WSTAGE;
        #pragma unroll
        for (int i = 0; i < 4; i++) {
            int c = tid + i * 256;            // 1024 chunks: 256 rows x 4 x 16B
            int row = c >> 2, seg = c & 3;
            cp16(dstb + (uint32_t)(row * SW + seg * 8) * 2,
                 src + (size_t)row * DJ + seg * 8);
        }
    };
    loadw(0); asm volatile("cp.async.commit_group;\n" ::: "memory");
    loadw(1); asm volatile("cp.async.commit_group;\n" ::: "memory");

    // ---- Phase 1: A = tanh(enc + pred), fp16, once ----
    const float* encp  = g_enc  + ((size_t)b * T_ + t0) * DJ;
    const float* predp = g_pred + ((size_t)b * U_ + u0) * DJ;
    for (int kc = 0; kc < DJ; kc += 64) {
        #pragma unroll
        for (int i = 0; i < 2; i++) {       // enc 16x64: 512 float2
            int idx = tid + i * 256;
            int rw = idx >> 5, kp = idx & 31;
            int t = t0 + rw;
            float2 ev = make_float2(0.f, 0.f);
            if (t < T_) ev = *(const float2*)(encp + (size_t)rw * DJ + kc + kp * 2);
            *(float2*)(encs + rw * 64 + kp * 2) = ev;
        }
        {   // pred 8x64: 256 float2
            int rw = tid >> 5, kp = tid & 31;
            int u = u0 + rw;
            float2 pv = make_float2(0.f, 0.f);
            if (u < U_) pv = *(const float2*)(predp + (size_t)rw * DJ + kc + kp * 2);
            *(float2*)(preds + rw * 64 + kp * 2) = pv;
        }
        __syncthreads();
        #pragma unroll
        for (int i = 0; i < 16; i++) {      // 128 rows x 32 half2
            int idx = tid + i * 256;
            int row = idx >> 5, kp = idx & 31;   // row = t-local*8 + u-local
            float2 e = *(const float2*)(encs + ((row >> 3) << 6) + kp * 2);
            float2 p = *(const float2*)(preds + ((row & 7) << 6) + kp * 2);
            half2 h = __floats2half2_rn(tanh_fast(e.x + p.x), tanh_fast(e.y + p.y));
            *(half2*)(As + row * SA + kc + kp * 2) = h;
        }
        __syncthreads();
    }

    // ---- Phase 2: 4 vocab tiles x 20 K-steps, double-buffered W ----
    float acc[4][8][4];
    #pragma unroll
    for (int mt = 0; mt < 4; mt++)
        #pragma unroll
        for (int nt = 0; nt < 8; nt++)
            #pragma unroll
            for (int c = 0; c < 4; c++) acc[mt][nt][c] = 0.f;

    int j = lane >> 3;
    int a_row_base = warp_m * 64 + (lane & 7) + (j & 1) * 8;
    int a_col_base = (j >> 1) * 4;
    int b_row_base = warp_n * 64 + (j >> 1) * 8 + (lane & 7);
    int b_col_base = (j & 1) * 4;

    for (int s = 0; s < NSTEPS; ++s) {
        asm volatile("cp.async.wait_group 1;\n" ::: "memory");
        __syncthreads();

        int kw0 = (s % STEPS_PER_TILE) * (KC / 2);   // word offset in As row
        uint32_t wbase = ws_u + (uint32_t)(s & 1) * WSTAGE;

        #pragma unroll
        for (int ks = 0; ks < 2; ks++) {
            uint32_t a[4][4];
            #pragma unroll
            for (int mt = 0; mt < 4; mt++)
                ldsm_x4(a[mt][0], a[mt][1], a[mt][2], a[mt][3],
                        as_u + (uint32_t)((a_row_base + mt * 16) * SAW
                                          + kw0 + ks * 8 + a_col_base) * 4);
            uint32_t bb[4][4];
            #pragma unroll
            for (int np = 0; np < 4; np++)
                ldsm_x4(bb[np][0], bb[np][1], bb[np][2], bb[np][3],
                        wbase + (uint32_t)((b_row_base + np * 16) * SWW
                                           + ks * 8 + b_col_base) * 4);
            #pragma unroll
            for (int mt = 0; mt < 4; mt++) {
                #pragma unroll
                for (int nt = 0; nt < 8; nt++) {
                    uint32_t bf0 = bb[nt >> 1][(nt & 1) * 2];
                    uint32_t bf1 = bb[nt >> 1][(nt & 1) * 2 + 1];
                    asm volatile(
                        "mma.sync.aligned.m16n8k16.row.col.f32.f16.f16.f32 "
                        "{%0,%1,%2,%3}, {%4,%5,%6,%7}, {%8,%9}, {%0,%1,%2,%3};\n"
                        : "+f"(acc[mt][nt][0]), "+f"(acc[mt][nt][1]),
                          "+f"(acc[mt][nt][2]), "+f"(acc[mt][nt][3])
                        : "r"(a[mt][0]), "r"(a[mt][1]), "r"(a[mt][2]), "r"(a[mt][3]),
                          "r"(bf0), "r"(bf1));
                }
            }
        }
        __syncthreads();

        if (s + 2 < NSTEPS) loadw(s + 2);
        asm volatile("cp.async.commit_group;\n" ::: "memory");

        if ((s % STEPS_PER_TILE) == STEPS_PER_TILE - 1) {
            int n0 = (s / STEPS_PER_TILE) * NTILE;
            #pragma unroll
            for (int nt = 0; nt < 8; nt++) {
                int n = n0 + warp_n * 64 + nt * 8 + tg * 2;
                float bo0 = __ldg(bout + n);
                float bo1 = __ldg(bout + n + 1);
                #pragma unroll
                for (int mt = 0; mt < 4; mt++) {
                    #pragma unroll
                    for (int h = 0; h < 2; h++) {
                        int row = warp_m * 64 + mt * 16 + g + h * 8;
                        int t = t0 + (row >> 3), u = u0 + (row & 7);
                        if (t < T_ && u < U_) {
                            size_t base = ((((size_t)b * T_ + t) * U_ + u) * V_) + n;
                            float2 v = make_float2(acc[mt][nt][h * 2] + bo0,
                                                   acc[mt][nt][h * 2 + 1] + bo1);
                            *(float2*)(out + base) = v;
                        }
                    }
                }
            }
            #pragma unroll
            for (int mt = 0; mt < 4; mt++)
                #pragma unroll
                for (int nt = 0; nt < 8; nt++)
                    #pragma unroll
                    for (int c = 0; c < 4; c++) acc[mt][nt][c] = 0.f;
        }
    }
    asm volatile("cp.async.wait_group 0;\n" ::: "memory");
}

// ---------------------------------------------------------------------------
extern "C" void kernel_launch(void* const* d_in, const int* in_sizes, int n_in,
                              void* d_out, int out_size) {
    const float* encoder_out   = (const float*)d_in[0];
    const float* predictor_out = (const float*)d_in[1];
    const float* W_enc  = (const float*)d_in[2];
    const float* b_enc  = (const float*)d_in[3];
    const float* W_pred = (const float*)d_in[4];
    const float* b_pred = (const float*)d_in[5];
    const float* W_out  = (const float*)d_in[6];
    const float* b_out  = (const float*)d_in[7];
    float* out = (float*)d_out;

    float* enc_buf;
    float* pred_buf;
    __half* wh_buf;
    cudaGetSymbolAddress((void**)&enc_buf,  g_enc);
    cudaGetSymbolAddress((void**)&pred_buf, g_pred);
    cudaGetSymbolAddress((void**)&wh_buf,   g_wh);

    cudaFuncSetAttribute(joint_kernel,
                         cudaFuncAttributeMaxDynamicSharedMemorySize, JOINT_SMEM);

    convert_w_kernel<<<(V_ * DJ / 2 + 255) / 256, 256>>>(W_out, wh_buf);

    {   // merged projections: z=0 enc (50 y-tiles), z=1 pred (13 y-tiles)
        dim3 grid(DJ / 64, (B_ * T_ + 31) / 32, 2);
        proj_kernel<<<grid, 256>>>(encoder_out, W_enc, b_enc, enc_buf,
                                   predictor_out, W_pred, b_pred, pred_buf);
    }

    // joint: 13 t-tiles x 7 u-tiles x 8 b = 728 CTAs
    joint_kernel<<<728, 256, JOINT_SMEM>>>(b_out, out);
}

// round 8
// speedup vs baseline: 2.7292x; 1.3260x over previous
#include <cuda_runtime.h>
#include <cuda_fp16.h>
#include <cstdint>

#define B_  8
#define T_  200
#define U_  50
#define DE  512
#define DP  640
#define DJ  640
#define V_  1024

#define MT     128                 // M rows per CTA (16 t x 8 u)
#define NTILE  256                 // vocab cols per CTA pass
#define NPASS  (V_ / NTILE)        // 4
#define KSTEPS (DJ / 16)           // 40 k16 steps

#define SA   648   // As stride halves; 324 words, %32=4 -> ldsm conflict-free
#define SAW  324

#define AS_BYTES   (MT * SA * 2)               // 165888
#define ENC_OFF    AS_BYTES
#define PRED_OFF   (ENC_OFF + 16 * 64 * 4)
#define JOINT_SMEM (PRED_OFF + 8 * 64 * 4)     // 172032

// Scratch
__device__ float  g_enc [B_ * T_ * DJ];
__device__ float  g_pred[B_ * U_ * DJ];
// W pre-shuffled into mma B-fragment order:
// uint4 index = (n16 * KSTEPS + kstep) * 32 + lane
//   16B = {b0,b1 of n8-frag (n16*16 + g), b0,b1 of n8-frag (n16*16 + 8 + g)}
//   where b0 = W[n][k0+tg*2, +1], b1 = W[n][k0+8+tg*2, +1], k0 = kstep*16
__device__ __align__(16) __half g_wh[V_ * DJ];

// ---------------------------------------------------------------------------
__device__ __forceinline__ uint32_t smem_u32(const void* p) {
    return (uint32_t)__cvta_generic_to_shared(p);
}
__device__ __forceinline__ void ldsm_x4(uint32_t& r0, uint32_t& r1, uint32_t& r2,
                                        uint32_t& r3, uint32_t a) {
    asm volatile("ldmatrix.sync.aligned.m8n8.x4.shared.b16 {%0,%1,%2,%3}, [%4];\n"
                 : "=r"(r0), "=r"(r1), "=r"(r2), "=r"(r3) : "r"(a));
}
__device__ __forceinline__ float tanh_fast(float x) {
    float y;
    asm("tanh.approx.f32 %0, %1;" : "=f"(y) : "f"(x));
    return y;
}
__device__ __forceinline__ uint32_t packh2(float a, float b) {
    half2 h = __floats2half2_rn(a, b);
    return *(uint32_t*)&h;
}

// ---------------------------------------------------------------------------
// W_out fp32 -> fp16, shuffled into B-fragment order (see g_wh comment).
// One thread per 16B output chunk: 64 n16-blocks x 40 ksteps x 32 lanes.
// ---------------------------------------------------------------------------
__global__ __launch_bounds__(256)
void convert_w_kernel(const float* __restrict__ W, uint4* __restrict__ Wh) {
    int tid = blockIdx.x * blockDim.x + threadIdx.x;   // 0..81919
    if (tid >= (V_ / 16) * KSTEPS * 32) return;
    int lane = tid & 31;
    int rest = tid >> 5;
    int ks = rest % KSTEPS;
    int n16 = rest / KSTEPS;
    int g = lane >> 2, tg = lane & 3;

    const float* r0p = W + (size_t)(n16 * 16 + g) * DJ + ks * 16 + tg * 2;
    const float* r1p = r0p + 8 * DJ;   // row +8
    float2 w0 = *(const float2*)(r0p);
    float2 w1 = *(const float2*)(r0p + 8);
    float2 w2 = *(const float2*)(r1p);
    float2 w3 = *(const float2*)(r1p + 8);
    uint4 o;
    o.x = packh2(w0.x, w0.y);
    o.y = packh2(w1.x, w1.y);
    o.z = packh2(w2.x, w2.y);
    o.w = packh2(w3.x, w3.y);
    Wh[tid] = o;
}

// ---------------------------------------------------------------------------
// Merged projection GEMMs: z=0 -> enc, z=1 -> pred. fp32, 32x64 tiles.
// ---------------------------------------------------------------------------
__global__ __launch_bounds__(256)
void proj_kernel(const float* __restrict__ Aenc, const float* __restrict__ Wenc,
                 const float* __restrict__ benc, float* __restrict__ Cenc,
                 const float* __restrict__ Apred, const float* __restrict__ Wpred,
                 const float* __restrict__ bpred, float* __restrict__ Cpred) {
    int z = blockIdx.z;
    const float* A    = z ? Apred : Aenc;
    const float* W    = z ? Wpred : Wenc;
    const float* bias = z ? bpred : benc;
    float*       C    = z ? Cpred : Cenc;
    int M = z ? (B_ * U_) : (B_ * T_);
    int D = z ? DP : DE;

    int m0 = blockIdx.y * 32;
    if (m0 >= M) return;
    int j0 = blockIdx.x * 64;

    __shared__ float As[32][17];
    __shared__ float Ws[64][17];
    int tid = threadIdx.x;
    int tx = tid & 15, ty = tid >> 4;

    float acc[2][4];
    #pragma unroll
    for (int i = 0; i < 2; i++)
        #pragma unroll
        for (int j = 0; j < 4; j++) acc[i][j] = 0.f;

    for (int kt = 0; kt < D; kt += 16) {
        #pragma unroll
        for (int i = 0; i < 2; i++) {
            int idx = tid + i * 256;
            int r = idx >> 4, k = idx & 15;
            int m = m0 + r;
            As[r][k] = (m < M) ? A[(size_t)m * D + kt + k] : 0.f;
        }
        #pragma unroll
        for (int i = 0; i < 4; i++) {
            int idx = tid + i * 256;
            int r = idx >> 4, k = idx & 15;
            Ws[r][k] = W[(size_t)(j0 + r) * D + kt + k];
        }
        __syncthreads();
        #pragma unroll
        for (int kk = 0; kk < 16; kk++) {
            float a0 = As[ty][kk], a1 = As[ty + 16][kk];
            float w[4];
            #pragma unroll
            for (int j = 0; j < 4; j++) w[j] = Ws[tx + j * 16][kk];
            #pragma unroll
            for (int j = 0; j < 4; j++) {
                acc[0][j] += a0 * w[j];
                acc[1][j] += a1 * w[j];
            }
        }
        __syncthreads();
    }
    #pragma unroll
    for (int i = 0; i < 2; i++) {
        int m = m0 + ty + i * 16;
        if (m >= M) continue;
        #pragma unroll
        for (int j = 0; j < 4; j++) {
            int jj = j0 + tx + j * 16;
            C[(size_t)m * DJ + jj] = acc[i][j] + bias[jj];
        }
    }
}

// ---------------------------------------------------------------------------
// Joint kernel: CTA = 128 M-rows (16t x 8u) x V=1024 in 4 passes of N=256.
// 256 threads = 8 warps (2m x 4n), warp tile 64x64 per pass.
// A = tanh(enc+pred) fp16 persistent in SMEM (built once, one barrier).
// B loaded DIRECTLY from gmem (pre-shuffled frag order, L1/L2-resident).
// Phase 2 has NO barriers: warps free-run.
// ---------------------------------------------------------------------------
extern __shared__ __align__(128) char dynsmem[];

__global__ __launch_bounds__(256, 1)
void joint_kernel(const float* __restrict__ bout, float* __restrict__ out) {
    half*  As    = (half*)dynsmem;
    float* encs  = (float*)(dynsmem + ENC_OFF);    // 16 x 64
    float* preds = (float*)(dynsmem + PRED_OFF);   // 8 x 64

    int tid = threadIdx.x;
    int wid = tid >> 5, lane = tid & 31;
    int g = lane >> 2, tg = lane & 3;
    int warp_m = wid >> 2, warp_n = wid & 3;   // 2 x 4

    int bx = blockIdx.x;               // 728 CTAs: 13 t-tiles x 7 u-tiles x 8 b
    int b = bx / 91, r = bx % 91;
    int tt = r % 13, ut = r / 13;
    int t0 = tt * 16, u0 = ut * 8;

    uint32_t as_u = smem_u32(As);

    // ---- Phase 1: A = tanh(enc + pred), fp16, once ----
    const float* encp  = g_enc  + ((size_t)b * T_ + t0) * DJ;
    const float* predp = g_pred + ((size_t)b * U_ + u0) * DJ;
    for (int kc = 0; kc < DJ; kc += 64) {
        #pragma unroll
        for (int i = 0; i < 2; i++) {       // enc 16x64: 512 float2
            int idx = tid + i * 256;
            int rw = idx >> 5, kp = idx & 31;
            int t = t0 + rw;
            float2 ev = make_float2(0.f, 0.f);
            if (t < T_) ev = *(const float2*)(encp + (size_t)rw * DJ + kc + kp * 2);
            *(float2*)(encs + rw * 64 + kp * 2) = ev;
        }
        {   // pred 8x64: 256 float2
            int rw = tid >> 5, kp = tid & 31;
            int u = u0 + rw;
            float2 pv = make_float2(0.f, 0.f);
            if (u < U_) pv = *(const float2*)(predp + (size_t)rw * DJ + kc + kp * 2);
            *(float2*)(preds + rw * 64 + kp * 2) = pv;
        }
        __syncthreads();
        #pragma unroll
        for (int i = 0; i < 16; i++) {      // 128 rows x 32 half2
            int idx = tid + i * 256;
            int row = idx >> 5, kp = idx & 31;   // row = t-local*8 + u-local
            float2 e = *(const float2*)(encs + ((row >> 3) << 6) + kp * 2);
            float2 p = *(const float2*)(preds + ((row & 7) << 6) + kp * 2);
            half2 h = __floats2half2_rn(tanh_fast(e.x + p.x), tanh_fast(e.y + p.y));
            *(half2*)(As + row * SA + kc + kp * 2) = h;
        }
        __syncthreads();
    }

    // ---- Phase 2: 4 vocab passes x 40 k16-steps. NO BARRIERS. ----
    int j = lane >> 3;
    int a_row_base = warp_m * 64 + (lane & 7) + (j & 1) * 8;
    int a_col_base = (j >> 1) * 4;

    const uint4* wsh = (const uint4*)g_wh;

    for (int np = 0; np < NPASS; np++) {
        float acc[4][8][4];
        #pragma unroll
        for (int mt = 0; mt < 4; mt++)
            #pragma unroll
            for (int nt = 0; nt < 8; nt++)
                #pragma unroll
                for (int c = 0; c < 4; c++) acc[mt][nt][c] = 0.f;

        // base n16 index for this warp/pass
        int n16b = np * (NTILE / 16) + warp_n * 4;
        const uint4* wp = wsh + ((size_t)n16b * KSTEPS) * 32 + lane;

        for (int ks = 0; ks < KSTEPS; ks++) {
            // B frags: 4 x LDG.128 (two n8 frags each)
            uint4 bq[4];
            #pragma unroll
            for (int p = 0; p < 4; p++)
                bq[p] = wp[((size_t)p * KSTEPS + ks) * 32];
            // A frags: 4 x ldsm.x4
            uint32_t a[4][4];
            #pragma unroll
            for (int mt = 0; mt < 4; mt++)
                ldsm_x4(a[mt][0], a[mt][1], a[mt][2], a[mt][3],
                        as_u + (uint32_t)((a_row_base + mt * 16) * SAW
                                          + ks * 8 + a_col_base) * 4);
            #pragma unroll
            for (int mt = 0; mt < 4; mt++) {
                #pragma unroll
                for (int nt = 0; nt < 8; nt++) {
                    uint32_t bf0 = (nt & 1) ? bq[nt >> 1].z : bq[nt >> 1].x;
                    uint32_t bf1 = (nt & 1) ? bq[nt >> 1].w : bq[nt >> 1].y;
                    asm volatile(
                        "mma.sync.aligned.m16n8k16.row.col.f32.f16.f16.f32 "
                        "{%0,%1,%2,%3}, {%4,%5,%6,%7}, {%8,%9}, {%0,%1,%2,%3};\n"
                        : "+f"(acc[mt][nt][0]), "+f"(acc[mt][nt][1]),
                          "+f"(acc[mt][nt][2]), "+f"(acc[mt][nt][3])
                        : "r"(a[mt][0]), "r"(a[mt][1]), "r"(a[mt][2]), "r"(a[mt][3]),
                          "r"(bf0), "r"(bf1));
                }
            }
        }

        // epilogue for this pass
        int n0 = np * NTILE;
        #pragma unroll
        for (int nt = 0; nt < 8; nt++) {
            int n = n0 + warp_n * 64 + nt * 8 + tg * 2;
            float bo0 = __ldg(bout + n);
            float bo1 = __ldg(bout + n + 1);
            #pragma unroll
            for (int mt = 0; mt < 4; mt++) {
                #pragma unroll
                for (int h = 0; h < 2; h++) {
                    int row = warp_m * 64 + mt * 16 + g + h * 8;
                    int t = t0 + (row >> 3), u = u0 + (row & 7);
                    if (t < T_ && u < U_) {
                        size_t base = ((((size_t)b * T_ + t) * U_ + u) * V_) + n;
                        float2 v = make_float2(acc[mt][nt][h * 2] + bo0,
                                               acc[mt][nt][h * 2 + 1] + bo1);
                        *(float2*)(out + base) = v;
                    }
                }
            }
        }
    }
}

// ---------------------------------------------------------------------------
extern "C" void kernel_launch(void* const* d_in, const int* in_sizes, int n_in,
                              void* d_out, int out_size) {
    const float* encoder_out   = (const float*)d_in[0];
    const float* predictor_out = (const float*)d_in[1];
    const float* W_enc  = (const float*)d_in[2];
    const float* b_enc  = (const float*)d_in[3];
    const float* W_pred = (const float*)d_in[4];
    const float* b_pred = (const float*)d_in[5];
    const float* W_out  = (const float*)d_in[6];
    const float* b_out  = (const float*)d_in[7];
    float* out = (float*)d_out;

    float* enc_buf;
    float* pred_buf;
    uint4* wh_buf;
    cudaGetSymbolAddress((void**)&enc_buf,  g_enc);
    cudaGetSymbolAddress((void**)&pred_buf, g_pred);
    cudaGetSymbolAddress((void**)&wh_buf,   g_wh);

    cudaFuncSetAttribute(joint_kernel,
                         cudaFuncAttributeMaxDynamicSharedMemorySize, JOINT_SMEM);

    // W_out -> fp16, frag-shuffled
    convert_w_kernel<<<((V_ / 16) * KSTEPS * 32 + 255) / 256, 256>>>(W_out, wh_buf);

    {   // merged projections: z=0 enc (50 y-tiles), z=1 pred (13 y-tiles)
        dim3 grid(DJ / 64, (B_ * T_ + 31) / 32, 2);
        proj_kernel<<<grid, 256>>>(encoder_out, W_enc, b_enc, enc_buf,
                                   predictor_out, W_pred, b_pred, pred_buf);
    }

    // joint: 13 t-tiles x 7 u-tiles x 8 b = 728 CTAs
    joint_kernel<<<728, 256, JOINT_SMEM>>>(b_out, out);
}

// round 10
// speedup vs baseline: 2.7467x; 1.0064x over previous
#include <cuda_runtime.h>
#include <cuda_fp16.h>
#include <cstdint>

#define B_  8
#define T_  200
#define U_  50
#define DE  512
#define DP  640
#define DJ  640
#define V_  1024

#define MT     128                 // M rows per CTA (16 t x 8 u)
#define NTILE  256                 // vocab cols per CTA pass
#define NPASS  (V_ / NTILE)        // 4
#define KSTEPS (DJ / 16)           // 40 k16 steps

#define SA   648   // As stride halves; 324 words, %32=4 -> ldsm conflict-free
#define SAW  324

#define AS_BYTES   (MT * SA * 2)               // 165888
#define ENC_OFF    AS_BYTES
#define PRED_OFF   (ENC_OFF + 16 * 64 * 4)
#define JOINT_SMEM (PRED_OFF + 8 * 64 * 4)     // 172032

// Scratch
__device__ float  g_enc [B_ * T_ * DJ];
__device__ float  g_pred[B_ * U_ * DJ];
// W pre-shuffled into mma B-fragment order:
// uint4 index = (n16 * KSTEPS + kstep) * 32 + lane
__device__ __align__(16) __half g_wh[V_ * DJ];

// ---------------------------------------------------------------------------
__device__ __forceinline__ uint32_t smem_u32(const void* p) {
    return (uint32_t)__cvta_generic_to_shared(p);
}
__device__ __forceinline__ void ldsm_x4(uint32_t& r0, uint32_t& r1, uint32_t& r2,
                                        uint32_t& r3, uint32_t a) {
    asm volatile("ldmatrix.sync.aligned.m8n8.x4.shared.b16 {%0,%1,%2,%3}, [%4];\n"
                 : "=r"(r0), "=r"(r1), "=r"(r2), "=r"(r3) : "r"(a));
}
__device__ __forceinline__ float tanh_fast(float x) {
    float y;
    asm("tanh.approx.f32 %0, %1;" : "=f"(y) : "f"(x));
    return y;
}
__device__ __forceinline__ uint32_t packh2(float a, float b) {
    half2 h = __floats2half2_rn(a, b);
    return *(uint32_t*)&h;
}

// ---------------------------------------------------------------------------
// W_out fp32 -> fp16, shuffled into B-fragment order.
// ---------------------------------------------------------------------------
__global__ __launch_bounds__(256)
void convert_w_kernel(const float* __restrict__ W, uint4* __restrict__ Wh) {
    int tid = blockIdx.x * blockDim.x + threadIdx.x;
    if (tid >= (V_ / 16) * KSTEPS * 32) return;
    int lane = tid & 31;
    int rest = tid >> 5;
    int ks = rest % KSTEPS;
    int n16 = rest / KSTEPS;
    int g = lane >> 2, tg = lane & 3;

    const float* r0p = W + (size_t)(n16 * 16 + g) * DJ + ks * 16 + tg * 2;
    const float* r1p = r0p + 8 * DJ;
    float2 w0 = *(const float2*)(r0p);
    float2 w1 = *(const float2*)(r0p + 8);
    float2 w2 = *(const float2*)(r1p);
    float2 w3 = *(const float2*)(r1p + 8);
    uint4 o;
    o.x = packh2(w0.x, w0.y);
    o.y = packh2(w1.x, w1.y);
    o.z = packh2(w2.x, w2.y);
    o.w = packh2(w3.x, w3.y);
    Wh[tid] = o;
}

// ---------------------------------------------------------------------------
// Merged projection GEMMs: z=0 -> enc, z=1 -> pred. fp32, 32x64 tiles.
// ---------------------------------------------------------------------------
__global__ __launch_bounds__(256)
void proj_kernel(const float* __restrict__ Aenc, const float* __restrict__ Wenc,
                 const float* __restrict__ benc, float* __restrict__ Cenc,
                 const float* __restrict__ Apred, const float* __restrict__ Wpred,
                 const float* __restrict__ bpred, float* __restrict__ Cpred) {
    int z = blockIdx.z;
    const float* A    = z ? Apred : Aenc;
    const float* W    = z ? Wpred : Wenc;
    const float* bias = z ? bpred : benc;
    float*       C    = z ? Cpred : Cenc;
    int M = z ? (B_ * U_) : (B_ * T_);
    int D = z ? DP : DE;

    int m0 = blockIdx.y * 32;
    if (m0 >= M) return;
    int j0 = blockIdx.x * 64;

    __shared__ float As[32][17];
    __shared__ float Ws[64][17];
    int tid = threadIdx.x;
    int tx = tid & 15, ty = tid >> 4;

    float acc[2][4];
    #pragma unroll
    for (int i = 0; i < 2; i++)
        #pragma unroll
        for (int j = 0; j < 4; j++) acc[i][j] = 0.f;

    for (int kt = 0; kt < D; kt += 16) {
        #pragma unroll
        for (int i = 0; i < 2; i++) {
            int idx = tid + i * 256;
            int r = idx >> 4, k = idx & 15;
            int m = m0 + r;
            As[r][k] = (m < M) ? A[(size_t)m * D + kt + k] : 0.f;
        }
        #pragma unroll
        for (int i = 0; i < 4; i++) {
            int idx = tid + i * 256;
            int r = idx >> 4, k = idx & 15;
            Ws[r][k] = W[(size_t)(j0 + r) * D + kt + k];
        }
        __syncthreads();
        #pragma unroll
        for (int kk = 0; kk < 16; kk++) {
            float a0 = As[ty][kk], a1 = As[ty + 16][kk];
            float w[4];
            #pragma unroll
            for (int j = 0; j < 4; j++) w[j] = Ws[tx + j * 16][kk];
            #pragma unroll
            for (int j = 0; j < 4; j++) {
                acc[0][j] += a0 * w[j];
                acc[1][j] += a1 * w[j];
            }
        }
        __syncthreads();
    }
    #pragma unroll
    for (int i = 0; i < 2; i++) {
        int m = m0 + ty + i * 16;
        if (m >= M) continue;
        #pragma unroll
        for (int j = 0; j < 4; j++) {
            int jj = j0 + tx + j * 16;
            C[(size_t)m * DJ + jj] = acc[i][j] + bias[jj];
        }
    }
}

// ---------------------------------------------------------------------------
// Joint kernel: CTA = 128 M-rows (16t x 8u) x V=1024 in 4 passes of N=256.
// Phase 2: no barriers; B frags double-buffered in registers (LDG prefetch).
// ---------------------------------------------------------------------------
extern __shared__ __align__(128) char dynsmem[];

__global__ __launch_bounds__(256, 1)
void joint_kernel(const float* __restrict__ bout, float* __restrict__ out) {
    half*  As    = (half*)dynsmem;
    float* encs  = (float*)(dynsmem + ENC_OFF);    // 16 x 64
    float* preds = (float*)(dynsmem + PRED_OFF);   // 8 x 64

    int tid = threadIdx.x;
    int wid = tid >> 5, lane = tid & 31;
    int g = lane >> 2, tg = lane & 3;
    int warp_m = wid >> 2, warp_n = wid & 3;   // 2 x 4

    int bx = blockIdx.x;               // 728 CTAs: 13 t-tiles x 7 u-tiles x 8 b
    int b = bx / 91, r = bx % 91;
    int tt = r % 13, ut = r / 13;
    int t0 = tt * 16, u0 = ut * 8;

    uint32_t as_u = smem_u32(As);

    // ---- Phase 1: A = tanh(enc + pred), fp16, once ----
    const float* encp  = g_enc  + ((size_t)b * T_ + t0) * DJ;
    const float* predp = g_pred + ((size_t)b * U_ + u0) * DJ;
    for (int kc = 0; kc < DJ; kc += 64) {
        #pragma unroll
        for (int i = 0; i < 2; i++) {       // enc 16x64: 512 float2
            int idx = tid + i * 256;
            int rw = idx >> 5, kp = idx & 31;
            int t = t0 + rw;
            float2 ev = make_float2(0.f, 0.f);
            if (t < T_) ev = *(const float2*)(encp + (size_t)rw * DJ + kc + kp * 2);
            *(float2*)(encs + rw * 64 + kp * 2) = ev;
        }
        {   // pred 8x64: 256 float2
            int rw = tid >> 5, kp = tid & 31;
            int u = u0 + rw;
            float2 pv = make_float2(0.f, 0.f);
            if (u < U_) pv = *(const float2*)(predp + (size_t)rw * DJ + kc + kp * 2);
            *(float2*)(preds + rw * 64 + kp * 2) = pv;
        }
        __syncthreads();
        #pragma unroll
        for (int i = 0; i < 16; i++) {      // 128 rows x 32 half2
            int idx = tid + i * 256;
            int row = idx >> 5, kp = idx & 31;
            float2 e = *(const float2*)(encs + ((row >> 3) << 6) + kp * 2);
            float2 p = *(const float2*)(preds + ((row & 7) << 6) + kp * 2);
            half2 h = __floats2half2_rn(tanh_fast(e.x + p.x), tanh_fast(e.y + p.y));
            *(half2*)(As + row * SA + kc + kp * 2) = h;
        }
        __syncthreads();
    }

    // ---- Phase 2: 4 vocab passes x 40 k16-steps. No barriers. ----
    int j = lane >> 3;
    int a_row_base = warp_m * 64 + (lane & 7) + (j & 1) * 8;
    int a_col_base = (j >> 1) * 4;

    const uint4* wsh = (const uint4*)g_wh;

    for (int np = 0; np < NPASS; np++) {
        float acc[4][8][4];
        #pragma unroll
        for (int mt = 0; mt < 4; mt++)
            #pragma unroll
            for (int nt = 0; nt < 8; nt++)
                #pragma unroll
                for (int c = 0; c < 4; c++) acc[mt][nt][c] = 0.f;

        int n16b = np * (NTILE / 16) + warp_n * 4;
        // 4 incremental pointers, one per n16 sub-block; step = 32 uint4 per kstep
        const uint4* wp0 = wsh + ((size_t)(n16b + 0) * KSTEPS) * 32 + lane;
        const uint4* wp1 = wsh + ((size_t)(n16b + 1) * KSTEPS) * 32 + lane;
        const uint4* wp2 = wsh + ((size_t)(n16b + 2) * KSTEPS) * 32 + lane;
        const uint4* wp3 = wsh + ((size_t)(n16b + 3) * KSTEPS) * 32 + lane;

        uint4 bq[2][4];
        bq[0][0] = *wp0; bq[0][1] = *wp1; bq[0][2] = *wp2; bq[0][3] = *wp3;

        #pragma unroll 2
        for (int ks = 0; ks < KSTEPS; ks++) {
            int cur = ks & 1, nxt = cur ^ 1;
            // prefetch next B frags (clamped to a valid in-bounds step; result
            // unused on the final iteration — keeps the loop body branch-free)
            int ksn = (ks + 1 < KSTEPS) ? (ks + 1) : ks;
            bq[nxt][0] = wp0[ksn * 32];
            bq[nxt][1] = wp1[ksn * 32];
            bq[nxt][2] = wp2[ksn * 32];
            bq[nxt][3] = wp3[ksn * 32];

            uint32_t a[4][4];
            #pragma unroll
            for (int mt = 0; mt < 4; mt++)
                ldsm_x4(a[mt][0], a[mt][1], a[mt][2], a[mt][3],
                        as_u + (uint32_t)((a_row_base + mt * 16) * SAW
                                          + ks * 8 + a_col_base) * 4);
            #pragma unroll
            for (int mt = 0; mt < 4; mt++) {
                #pragma unroll
                for (int nt = 0; nt < 8; nt++) {
                    uint32_t bf0 = (nt & 1) ? bq[cur][nt >> 1].z : bq[cur][nt >> 1].x;
                    uint32_t bf1 = (nt & 1) ? bq[cur][nt >> 1].w : bq[cur][nt >> 1].y;
                    asm volatile(
                        "mma.sync.aligned.m16n8k16.row.col.f32.f16.f16.f32 "
                        "{%0,%1,%2,%3}, {%4,%5,%6,%7}, {%8,%9}, {%0,%1,%2,%3};\n"
                        : "+f"(acc[mt][nt][0]), "+f"(acc[mt][nt][1]),
                          "+f"(acc[mt][nt][2]), "+f"(acc[mt][nt][3])
                        : "r"(a[mt][0]), "r"(a[mt][1]), "r"(a[mt][2]), "r"(a[mt][3]),
                          "r"(bf0), "r"(bf1));
                }
            }
        }

        // epilogue for this pass
        int n0 = np * NTILE;
        #pragma unroll
        for (int nt = 0; nt < 8; nt++) {
            int n = n0 + warp_n * 64 + nt * 8 + tg * 2;
            float bo0 = __ldg(bout + n);
            float bo1 = __ldg(bout + n + 1);
            #pragma unroll
            for (int mt = 0; mt < 4; mt++) {
                #pragma unroll
                for (int h = 0; h < 2; h++) {
                    int row = warp_m * 64 + mt * 16 + g + h * 8;
                    int t = t0 + (row >> 3), u = u0 + (row & 7);
                    if (t < T_ && u < U_) {
                        size_t base = ((((size_t)b * T_ + t) * U_ + u) * V_) + n;
                        float2 v = make_float2(acc[mt][nt][h * 2] + bo0,
                                               acc[mt][nt][h * 2 + 1] + bo1);
                        *(float2*)(out + base) = v;
                    }
                }
            }
        }
    }
}

// ---------------------------------------------------------------------------
extern "C" void kernel_launch(void* const* d_in, const int* in_sizes, int n_in,
                              void* d_out, int out_size) {
    const float* encoder_out   = (const float*)d_in[0];
    const float* predictor_out = (const float*)d_in[1];
    const float* W_enc  = (const float*)d_in[2];
    const float* b_enc  = (const float*)d_in[3];
    const float* W_pred = (const float*)d_in[4];
    const float* b_pred = (const float*)d_in[5];
    const float* W_out  = (const float*)d_in[6];
    const float* b_out  = (const float*)d_in[7];
    float* out = (float*)d_out;

    float* enc_buf;
    float* pred_buf;
    uint4* wh_buf;
    cudaGetSymbolAddress((void**)&enc_buf,  g_enc);
    cudaGetSymbolAddress((void**)&pred_buf, g_pred);
    cudaGetSymbolAddress((void**)&wh_buf,   g_wh);

    cudaFuncSetAttribute(joint_kernel,
                         cudaFuncAttributeMaxDynamicSharedMemorySize, JOINT_SMEM);

    convert_w_kernel<<<((V_ / 16) * KSTEPS * 32 + 255) / 256, 256>>>(W_out, wh_buf);

    {   // merged projections
        dim3 grid(DJ / 64, (B_ * T_ + 31) / 32, 2);
        proj_kernel<<<grid, 256>>>(encoder_out, W_enc, b_enc, enc_buf,
                                   predictor_out, W_pred, b_pred, pred_buf);
    }

    joint_kernel<<<728, 256, JOINT_SMEM>>>(b_out, out);
}